// round 1
// baseline (speedup 1.0000x reference)
#include <cuda_runtime.h>
#include <math.h>

#define NT 1024   // tokens
#define NH 1024   // hidden
#define NF 4096   // ffn
#define NE 8      // experts
#define NK 2      // top-k

// ---- device scratch (static globals; no allocation) ----
__device__ int   g_sel [NT * NK];
__device__ float g_rw  [NT * NK];
__device__ int   g_cnt [NE];
__device__ int   g_off [NE];
__device__ int   g_cur [NE];
__device__ int   g_tok [NT * NK];
__device__ float g_tokw[NT * NK];
// intermediate gelu activations: one row per (expert, slot) assignment (+ slack for tile overrun clamp)
__device__ float g_h[(NT * NK + 64) * NF];

// ---- packed f32x2 helpers ----
__device__ __forceinline__ unsigned long long pk2(float lo, float hi) {
    unsigned long long r;
    asm("mov.b64 %0, {%1, %2};" : "=l"(r) : "f"(lo), "f"(hi));
    return r;
}
__device__ __forceinline__ float2 upk2(unsigned long long v) {
    float2 r;
    asm("mov.b64 {%0, %1}, %2;" : "=f"(r.x), "=f"(r.y) : "l"(v));
    return r;
}
__device__ __forceinline__ void fma2(unsigned long long& d, unsigned long long a, unsigned long long b) {
    asm("fma.rn.f32x2 %0, %1, %2, %0;" : "+l"(d) : "l"(a), "l"(b));
}
__device__ __forceinline__ float gelu_exact(float v) {
    return 0.5f * v * (1.0f + erff(v * 0.70710678118654752f));
}

// ---- init: zero output + counters ----
__global__ void init_kernel(float* __restrict__ out, int n) {
    int i = blockIdx.x * blockDim.x + threadIdx.x;
    if (i < n) out[i] = 0.0f;
    if (i < NE) { g_cnt[i] = 0; g_cur[i] = 0; }
}

// ---- router: logits, top-2, softmax weights, per-expert counts ----
__global__ void router_kernel(const float* __restrict__ x,
                              const float* __restrict__ gw,
                              const float* __restrict__ gb) {
    __shared__ float4 sg[NE * NH / 4];  // 32 KB: full gate matrix
    int tid = threadIdx.x;
    for (int i = tid; i < NE * NH / 4; i += blockDim.x)
        sg[i] = ((const float4*)gw)[i];
    __syncthreads();

    int t = blockIdx.x * blockDim.x + tid;
    const float4* xr = (const float4*)(x + (size_t)t * NH);
    float acc[NE];
#pragma unroll
    for (int e = 0; e < NE; e++) acc[e] = gb[e];
    for (int i = 0; i < NH / 4; i++) {
        float4 xv = xr[i];
#pragma unroll
        for (int e = 0; e < NE; e++) {
            float4 g = sg[e * (NH / 4) + i];
            acc[e] += xv.x * g.x + xv.y * g.y + xv.z * g.z + xv.w * g.w;
        }
    }
    // top-2 (first occurrence wins on ties, matching jax top_k)
    int i0 = 0; float l0 = acc[0];
#pragma unroll
    for (int e = 1; e < NE; e++) if (acc[e] > l0) { l0 = acc[e]; i0 = e; }
    int i1 = -1; float l1 = -3.4e38f;
#pragma unroll
    for (int e = 0; e < NE; e++) if (e != i0 && acc[e] > l1) { l1 = acc[e]; i1 = e; }
    float p0 = 1.0f / (1.0f + expf(l1 - l0));  // softmax over [l0, l1], l0 >= l1
    g_sel[t * 2 + 0] = i0; g_sel[t * 2 + 1] = i1;
    g_rw [t * 2 + 0] = p0; g_rw [t * 2 + 1] = 1.0f - p0;
    atomicAdd(&g_cnt[i0], 1);
    atomicAdd(&g_cnt[i1], 1);
}

// ---- exclusive scan over 8 counts ----
__global__ void scan_kernel() {
    int o = 0;
    for (int e = 0; e < NE; e++) { g_off[e] = o; o += g_cnt[e]; }
}

// ---- scatter tokens into per-expert lists ----
__global__ void fill_kernel() {
    int t = blockIdx.x * blockDim.x + threadIdx.x;
    if (t >= NT) return;
    for (int k = 0; k < NK; k++) {
        int e = g_sel[t * 2 + k];
        int pos = atomicAdd(&g_cur[e], 1);
        int idx = g_off[e] + pos;
        g_tok[idx]  = t;
        g_tokw[idx] = g_rw[t * 2 + k];
    }
}

// ---- GEMM1: h[slot, n] = gelu( x[tok[slot]] @ w1[e] + b1[e] ), 64x64x16 tiles ----
__global__ __launch_bounds__(256, 2)
void gemm1_kernel(const float* __restrict__ x,
                  const float* __restrict__ w1,
                  const float* __restrict__ b1) {
    const int e = blockIdx.z;
    const int cnt = g_cnt[e];
    const int m0 = blockIdx.y * 64;
    if (m0 >= cnt) return;
    const int off = g_off[e];
    const int n0 = blockIdx.x * 64;

    __shared__ __align__(16) float As[16][68];
    __shared__ __align__(16) float Bs[16][68];
    __shared__ int stok[64];

    const int tid = threadIdx.x;
    if (tid < 64) {
        int mg = m0 + tid;
        stok[tid] = g_tok[off + ((mg < cnt) ? mg : 0)];
    }
    __syncthreads();

    const int tx = tid & 15, ty = tid >> 4;
    const int am = tid >> 2, ak = (tid & 3) * 4;
    const int bk = tid >> 4, bn = (tid & 15) * 4;

    const float* arow = x + (size_t)stok[am] * NH + ak;
    const float* bptr = w1 + (size_t)e * NH * NF + (size_t)bk * NF + n0 + bn;

    float4 aReg = *(const float4*)arow;
    float4 bReg = *(const float4*)bptr;

    unsigned long long acc[4][2] = {};

    for (int kt = 0; kt < NH / 16; kt++) {
        As[ak + 0][am] = aReg.x; As[ak + 1][am] = aReg.y;
        As[ak + 2][am] = aReg.z; As[ak + 3][am] = aReg.w;
        *(float4*)&Bs[bk][bn] = bReg;
        __syncthreads();
        if (kt + 1 < NH / 16) {
            aReg = *(const float4*)(arow + (kt + 1) * 16);
            bReg = *(const float4*)(bptr + (size_t)(kt + 1) * 16 * NF);
        }
#pragma unroll
        for (int k = 0; k < 16; k++) {
            float4 av = *(const float4*)&As[k][ty * 4];
            ulonglong2 bv = *(const ulonglong2*)&Bs[k][tx * 4];
            unsigned long long a0 = pk2(av.x, av.x), a1 = pk2(av.y, av.y);
            unsigned long long a2 = pk2(av.z, av.z), a3 = pk2(av.w, av.w);
            fma2(acc[0][0], a0, bv.x); fma2(acc[0][1], a0, bv.y);
            fma2(acc[1][0], a1, bv.x); fma2(acc[1][1], a1, bv.y);
            fma2(acc[2][0], a2, bv.x); fma2(acc[2][1], a2, bv.y);
            fma2(acc[3][0], a3, bv.x); fma2(acc[3][1], a3, bv.y);
        }
        __syncthreads();
    }

    const float* b1p = b1 + (size_t)e * NF + n0 + tx * 4;
#pragma unroll
    for (int i = 0; i < 4; i++) {
        int mg = m0 + ty * 4 + i;
        if (mg >= cnt) break;
        float2 c0 = upk2(acc[i][0]), c1 = upk2(acc[i][1]);
        float* hp = g_h + (size_t)(off + mg) * NF + n0 + tx * 4;
        hp[0] = gelu_exact(c0.x + b1p[0]);
        hp[1] = gelu_exact(c0.y + b1p[1]);
        hp[2] = gelu_exact(c1.x + b1p[2]);
        hp[3] = gelu_exact(c1.y + b1p[3]);
    }
}

// ---- GEMM2: out[tok] += rw * ( h[slot] @ w2[e] + b2[e] ), atomic scatter ----
__global__ __launch_bounds__(256, 2)
void gemm2_kernel(const float* __restrict__ w2,
                  const float* __restrict__ b2,
                  float* __restrict__ out) {
    const int e = blockIdx.z;
    const int cnt = g_cnt[e];
    const int m0 = blockIdx.y * 64;
    if (m0 >= cnt) return;
    const int off = g_off[e];
    const int n0 = blockIdx.x * 64;

    __shared__ __align__(16) float As[16][68];
    __shared__ __align__(16) float Bs[16][68];
    __shared__ int   stok[64];
    __shared__ float swt[64];

    const int tid = threadIdx.x;
    if (tid < 64) {
        int mg = m0 + tid;
        int mgc = (mg < cnt) ? mg : (cnt - 1);
        stok[tid] = g_tok[off + mgc];
        swt[tid]  = g_tokw[off + mgc];
    }
    __syncthreads();

    const int tx = tid & 15, ty = tid >> 4;
    const int am = tid >> 2, ak = (tid & 3) * 4;
    const int bk = tid >> 4, bn = (tid & 15) * 4;

    int mga = m0 + am; if (mga >= cnt) mga = cnt - 1;
    const float* arow = g_h + (size_t)(off + mga) * NF + ak;
    const float* bptr = w2 + (size_t)e * NF * NH + (size_t)bk * NH + n0 + bn;

    float4 aReg = *(const float4*)arow;
    float4 bReg = *(const float4*)bptr;

    unsigned long long acc[4][2] = {};

    for (int kt = 0; kt < NF / 16; kt++) {
        As[ak + 0][am] = aReg.x; As[ak + 1][am] = aReg.y;
        As[ak + 2][am] = aReg.z; As[ak + 3][am] = aReg.w;
        *(float4*)&Bs[bk][bn] = bReg;
        __syncthreads();
        if (kt + 1 < NF / 16) {
            aReg = *(const float4*)(arow + (kt + 1) * 16);
            bReg = *(const float4*)(bptr + (size_t)(kt + 1) * 16 * NH);
        }
#pragma unroll
        for (int k = 0; k < 16; k++) {
            float4 av = *(const float4*)&As[k][ty * 4];
            ulonglong2 bv = *(const ulonglong2*)&Bs[k][tx * 4];
            unsigned long long a0 = pk2(av.x, av.x), a1 = pk2(av.y, av.y);
            unsigned long long a2 = pk2(av.z, av.z), a3 = pk2(av.w, av.w);
            fma2(acc[0][0], a0, bv.x); fma2(acc[0][1], a0, bv.y);
            fma2(acc[1][0], a1, bv.x); fma2(acc[1][1], a1, bv.y);
            fma2(acc[2][0], a2, bv.x); fma2(acc[2][1], a2, bv.y);
            fma2(acc[3][0], a3, bv.x); fma2(acc[3][1], a3, bv.y);
        }
        __syncthreads();
    }

    const float* b2p = b2 + (size_t)e * NH + n0 + tx * 4;
#pragma unroll
    for (int i = 0; i < 4; i++) {
        int mg = m0 + ty * 4 + i;
        if (mg >= cnt) break;
        float wgt = swt[mg - m0];
        float* op = out + (size_t)stok[mg - m0] * NH + n0 + tx * 4;
        float2 c0 = upk2(acc[i][0]), c1 = upk2(acc[i][1]);
        atomicAdd(&op[0], wgt * (c0.x + b2p[0]));
        atomicAdd(&op[1], wgt * (c0.y + b2p[1]));
        atomicAdd(&op[2], wgt * (c1.x + b2p[2]));
        atomicAdd(&op[3], wgt * (c1.y + b2p[3]));
    }
}

extern "C" void kernel_launch(void* const* d_in, const int* in_sizes, int n_in,
                              void* d_out, int out_size) {
    const float* x  = (const float*)d_in[0];
    const float* gw = (const float*)d_in[1];
    const float* gb = (const float*)d_in[2];
    const float* w1 = (const float*)d_in[3];
    const float* b1 = (const float*)d_in[4];
    const float* w2 = (const float*)d_in[5];
    const float* b2 = (const float*)d_in[6];
    float* out = (float*)d_out;

    init_kernel<<<(out_size + 511) / 512, 512>>>(out, out_size);
    router_kernel<<<NT / 128, 128>>>(x, gw, gb);
    scan_kernel<<<1, 1>>>();
    fill_kernel<<<NT / 256, 256>>>();
    dim3 g1(NF / 64, NT / 64, NE);
    gemm1_kernel<<<g1, 256>>>(x, w1, b1);
    dim3 g2(NH / 64, NT / 64, NE);
    gemm2_kernel<<<g2, 256>>>(w2, b2, out);
}

// round 3
// speedup vs baseline: 2.3050x; 2.3050x over previous
#include <cuda_runtime.h>
#include <cstdint>
#include <math.h>

#define NT 1024
#define NH 1024
#define NF 4096
#define NE 8
#define NK 2

// ---- device scratch ----
__device__ int   g_sel [NT*NK];
__device__ float g_rw  [NT*NK];
__device__ int   g_slot[NT*NK];
__device__ int   g_cnt [NE];
__device__ int   g_off [NE];
__device__ int   g_cur [NE];
__device__ int   g_tok [NT*NK];
__device__ float g_h[(size_t)(NT*NK)*NF];          // gelu activations per slot
__device__ float g_y[2][(size_t)(NT*NK)*NH];       // GEMM2 split-K partials per slot

// ---- helpers ----
__device__ __forceinline__ uint32_t smem_u32(const void* p){
    uint32_t a; asm("{ .reg .u64 t; cvta.to.shared.u64 t, %1; cvt.u32.u64 %0, t; }":"=r"(a):"l"(p)); return a;
}
__device__ __forceinline__ void cpa16(uint32_t s, const void* g){
    asm volatile("cp.async.cg.shared.global [%0], [%1], 16;"::"r"(s),"l"(g));
}
__device__ __forceinline__ void cpa_commit(){ asm volatile("cp.async.commit_group;"); }
template<int N> __device__ __forceinline__ void cpa_wait(){ asm volatile("cp.async.wait_group %0;"::"n"(N)); }
__device__ __forceinline__ uint32_t f2tf(float f){
    uint32_t r; asm("cvt.rna.tf32.f32 %0, %1;":"=r"(r):"f"(f)); return r;
}
__device__ __forceinline__ void mma8(float* d, const uint32_t* a, const uint32_t* b){
    asm volatile("mma.sync.aligned.m16n8k8.row.col.f32.tf32.tf32.f32 "
        "{%0,%1,%2,%3}, {%4,%5,%6,%7}, {%8,%9}, {%0,%1,%2,%3};"
        : "+f"(d[0]),"+f"(d[1]),"+f"(d[2]),"+f"(d[3])
        : "r"(a[0]),"r"(a[1]),"r"(a[2]),"r"(a[3]),"r"(b[0]),"r"(b[1]));
}
__device__ __forceinline__ float gelu_exact(float v){
    return 0.5f * v * (1.0f + erff(v * 0.70710678118654752f));
}

// ---- init / router / scan / fill ----
__global__ void init_kernel(){
    int i = threadIdx.x;
    if (i < NE){ g_cnt[i]=0; g_cur[i]=0; }
}

__global__ void router_kernel(const float* __restrict__ x,
                              const float* __restrict__ gw,
                              const float* __restrict__ gb){
    __shared__ float4 sg[NE*NH/4];
    int tid = threadIdx.x;
    for (int i = tid; i < NE*NH/4; i += blockDim.x) sg[i] = ((const float4*)gw)[i];
    __syncthreads();
    int t = blockIdx.x*blockDim.x + tid;
    const float4* xr = (const float4*)(x + (size_t)t*NH);
    float acc[NE];
#pragma unroll
    for (int e=0;e<NE;e++) acc[e] = gb[e];
    for (int i=0;i<NH/4;i++){
        float4 xv = xr[i];
#pragma unroll
        for (int e=0;e<NE;e++){
            float4 g = sg[e*(NH/4)+i];
            acc[e] += xv.x*g.x + xv.y*g.y + xv.z*g.z + xv.w*g.w;
        }
    }
    int i0=0; float l0=acc[0];
#pragma unroll
    for (int e=1;e<NE;e++) if (acc[e]>l0){ l0=acc[e]; i0=e; }
    int i1=-1; float l1=-3.4e38f;
#pragma unroll
    for (int e=0;e<NE;e++) if (e!=i0 && acc[e]>l1){ l1=acc[e]; i1=e; }
    float p0 = 1.0f/(1.0f+expf(l1-l0));
    g_sel[t*2+0]=i0; g_sel[t*2+1]=i1;
    g_rw [t*2+0]=p0; g_rw [t*2+1]=1.0f-p0;
    atomicAdd(&g_cnt[i0],1);
    atomicAdd(&g_cnt[i1],1);
}

__global__ void scan_kernel(){
    int o=0;
    for (int e=0;e<NE;e++){ g_off[e]=o; o+=g_cnt[e]; }
}

__global__ void fill_kernel(){
    int t = blockIdx.x*blockDim.x + threadIdx.x;
    if (t >= NT) return;
    for (int k=0;k<NK;k++){
        int e = g_sel[t*2+k];
        int pos = atomicAdd(&g_cur[e],1);
        int idx = g_off[e]+pos;
        g_tok[idx]   = t;
        g_slot[t*2+k]= idx;
    }
}

// ---- grouped tf32 mma.sync GEMM ----
// MODE 1: g_h[slot] = gelu( x[tok] @ w1[e] + b1[e] )     K=NH,  ldB=NF, out width NF
// MODE 2: g_y[ks][slot] = g_h[slot] @ w2[e]  (K split 2) K=2048,ldB=NH, out width NH
// CTA 128x128, BK=32, 128 threads = 4 warps (2x2) of 64x64 warp tiles.
// 3-stage cp.async pipeline; A stride 36 floats, B stride 132 floats (conflict-free frags).

#define ASTR 36
#define BSTR 132
#define STG_A (128*ASTR)            // floats
#define STG_B (32*BSTR)
#define STG_F (STG_A + STG_B)       // 8832 floats
#define SMEM_SZ (3*STG_F*4)         // 105984 bytes

template<int MODE>
__global__ __launch_bounds__(128, 2)
void moe_gemm(const float* __restrict__ Asrc,
              const float* __restrict__ W,
              const float* __restrict__ bias){
    const int z   = blockIdx.z;
    const int e   = (MODE==1) ? z : (z & 7);
    const int ks  = (MODE==1) ? 0 : (z >> 3);
    const int cnt = g_cnt[e];
    const int m0  = blockIdx.y * 128;
    if (m0 >= cnt) return;
    const int off = g_off[e];
    const int n0  = blockIdx.x * 128;
    const int ldB = (MODE==1) ? NF : NH;
    const int Kfull = (MODE==1) ? NH : NF;
    const int Kloc  = (MODE==1) ? NH : NF/2;
    const int k0    = (MODE==1) ? 0  : ks * (NF/2);
    const int KT    = Kloc / 32;

    extern __shared__ float smem[];
    const uint32_t sb = smem_u32(smem);
    const int tid = threadIdx.x, wid = tid>>5, lane = tid&31;
    const int g = lane>>2, tg = lane&3;
    const int wm = wid&1, wn = wid>>1;

    // per-thread global A row pointers (8 rows, clamped gather)
    const float* aptr[8];
#pragma unroll
    for (int j=0;j<8;j++){
        int mi = m0 + j*16 + (tid>>3);
        int ci = (mi < cnt) ? mi : (cnt-1);
        if (MODE==1) aptr[j] = Asrc + (size_t)g_tok[off+ci]*NH + (tid&7)*4;
        else         aptr[j] = Asrc + (size_t)(off+ci)*NF + k0 + (tid&7)*4;
    }
    const float* bptr = W + (size_t)e*Kfull*ldB + (size_t)(k0 + (tid>>5))*ldB + n0 + (tid&31)*4;

    // smem dst offsets (bytes)
    const uint32_t adst = sb + ((tid>>3)*ASTR + (tid&7)*4)*4;
    const uint32_t bdst = sb + (STG_A + (tid>>5)*BSTR + (tid&31)*4)*4;

    // stage loader
    auto load_stage = [&](int s, int kt){
        uint32_t ab = adst + s*STG_F*4;
        uint32_t bb = bdst + s*STG_F*4;
#pragma unroll
        for (int j=0;j<8;j++)
            cpa16(ab + j*16*ASTR*4, aptr[j] + kt*32);
#pragma unroll
        for (int j=0;j<8;j++)
            cpa16(bb + j*4*BSTR*4, bptr + ((size_t)kt*32 + j*4)*ldB);
    };

    load_stage(0, 0); cpa_commit();
    load_stage(1, 1); cpa_commit();

    float acc[4][8][4];
#pragma unroll
    for (int i=0;i<4;i++)
#pragma unroll
        for (int j=0;j<8;j++)
#pragma unroll
            for (int r=0;r<4;r++) acc[i][j][r] = 0.0f;

    int s = 0;
    for (int kt = 0; kt < KT; kt++){
        cpa_wait<1>();
        __syncthreads();
        const float* sA = smem + s*STG_F;
        const float* sB = sA + STG_A;
#pragma unroll
        for (int kstep=0;kstep<4;kstep++){
            uint32_t af[4][4];
#pragma unroll
            for (int i=0;i<4;i++){
                const float* pa = sA + (wm*64 + i*16 + g)*ASTR + kstep*8 + tg;
                af[i][0] = f2tf(pa[0]);
                af[i][1] = f2tf(pa[8*ASTR]);
                af[i][2] = f2tf(pa[4]);
                af[i][3] = f2tf(pa[8*ASTR+4]);
            }
            uint32_t bf[8][2];
#pragma unroll
            for (int j=0;j<8;j++){
                const float* pb = sB + (kstep*8 + tg)*BSTR + wn*64 + j*8 + g;
                bf[j][0] = f2tf(pb[0]);
                bf[j][1] = f2tf(pb[4*BSTR]);
            }
#pragma unroll
            for (int i=0;i<4;i++)
#pragma unroll
                for (int j=0;j<8;j++)
                    mma8(acc[i][j], af[i], bf[j]);
        }
        __syncthreads();
        if (kt + 2 < KT) load_stage((s+2)%3, kt+2);
        cpa_commit();
        s = (s+1)%3;
    }

    // ---- epilogue ----
    if (MODE == 1){
        const float* bp = bias + (size_t)e*NF + n0 + wn*64;
#pragma unroll
        for (int i=0;i<4;i++){
            int r0 = m0 + wm*64 + i*16 + g;
            int r1 = r0 + 8;
#pragma unroll
            for (int j=0;j<8;j++){
                int c = j*8 + tg*2;
                float b0 = __ldg(bp + c), b1v = __ldg(bp + c + 1);
                if (r0 < cnt){
                    float* o = g_h + (size_t)(off+r0)*NF + n0 + wn*64 + c;
                    float2 v; v.x = gelu_exact(acc[i][j][0] + b0);
                              v.y = gelu_exact(acc[i][j][1] + b1v);
                    *(float2*)o = v;
                }
                if (r1 < cnt){
                    float* o = g_h + (size_t)(off+r1)*NF + n0 + wn*64 + c;
                    float2 v; v.x = gelu_exact(acc[i][j][2] + b0);
                              v.y = gelu_exact(acc[i][j][3] + b1v);
                    *(float2*)o = v;
                }
            }
        }
    } else {
        float* Yb = g_y[ks];
#pragma unroll
        for (int i=0;i<4;i++){
            int r0 = m0 + wm*64 + i*16 + g;
            int r1 = r0 + 8;
#pragma unroll
            for (int j=0;j<8;j++){
                int c = n0 + wn*64 + j*8 + tg*2;
                if (r0 < cnt)
                    *(float2*)(Yb + (size_t)(off+r0)*NH + c) = make_float2(acc[i][j][0], acc[i][j][1]);
                if (r1 < cnt)
                    *(float2*)(Yb + (size_t)(off+r1)*NH + c) = make_float2(acc[i][j][2], acc[i][j][3]);
            }
        }
    }
}

// ---- combine: out[t] = sum_k rw_k * ( g_y[0][slot_k] + g_y[1][slot_k] + b2[e_k] ) ----
__global__ void combine_kernel(const float* __restrict__ b2, float* __restrict__ out){
    int idx = blockIdx.x*blockDim.x + threadIdx.x;   // T * NH/4 threads
    int t  = idx >> 8;          // NH/4 = 256
    int h4 = (idx & 255) * 4;
    float4 a = make_float4(0.f,0.f,0.f,0.f);
#pragma unroll
    for (int k=0;k<2;k++){
        int e = g_sel[t*2+k];
        float w = g_rw[t*2+k];
        int sl = g_slot[t*2+k];
        float4 y0 = *(const float4*)&g_y[0][(size_t)sl*NH + h4];
        float4 y1 = *(const float4*)&g_y[1][(size_t)sl*NH + h4];
        float4 bb = *(const float4*)&b2[(size_t)e*NH + h4];
        a.x += w*(y0.x+y1.x+bb.x);
        a.y += w*(y0.y+y1.y+bb.y);
        a.z += w*(y0.z+y1.z+bb.z);
        a.w += w*(y0.w+y1.w+bb.w);
    }
    *(float4*)&out[(size_t)t*NH + h4] = a;
}

extern "C" void kernel_launch(void* const* d_in, const int* in_sizes, int n_in,
                              void* d_out, int out_size){
    const float* x  = (const float*)d_in[0];
    const float* gw = (const float*)d_in[1];
    const float* gb = (const float*)d_in[2];
    const float* w1 = (const float*)d_in[3];
    const float* b1 = (const float*)d_in[4];
    const float* w2 = (const float*)d_in[5];
    const float* b2 = (const float*)d_in[6];
    float* out = (float*)d_out;

    cudaFuncSetAttribute(moe_gemm<1>, cudaFuncAttributeMaxDynamicSharedMemorySize, SMEM_SZ);
    cudaFuncSetAttribute(moe_gemm<2>, cudaFuncAttributeMaxDynamicSharedMemorySize, SMEM_SZ);

    init_kernel<<<1, 32>>>();
    router_kernel<<<NT/128, 128>>>(x, gw, gb);
    scan_kernel<<<1, 1>>>();
    fill_kernel<<<NT/256, 256>>>();

    // need g_h base pointer for MODE2 A-source: take address via symbol on device is
    // implicit (g_h is a __device__ array; pass nullptr and use g_h directly? MODE2
    // uses Asrc param) -> get device pointer via cudaGetSymbolAddress is not
    // graph-unsafe (host API, no alloc), but simpler: MODE2 ignores Asrc==nullptr?
    // We must pass a real pointer: use cudaGetSymbolAddress once per launch.
    void* ghp = nullptr;
    cudaGetSymbolAddress(&ghp, g_h);

    dim3 g1(NF/128, 8, NE);        // 32 x 8 x 8
    moe_gemm<1><<<g1, 128, SMEM_SZ>>>(x, w1, b1);
    dim3 g2(NH/128, 8, NE*2);      // 8 x 8 x 16
    moe_gemm<2><<<g2, 128, SMEM_SZ>>>((const float*)ghp, w2, nullptr);

    combine_kernel<<<(NT*NH/4)/256, 256>>>(b2, out);
}